// round 15
// baseline (speedup 1.0000x reference)
#include <cuda_runtime.h>
#include <math.h>
#include <math_constants.h>

#ifndef CUDART_INF_F
#define CUDART_INF_F __int_as_float(0x7f800000)
#endif

// ---------------------------------------------------------------------------
// AdaptivePrecisionKVCache — R14: two-kernel pipeline, finalize eliminated.
//   small bin: |x| <= 0.01, levels = 15 ; large bin: |x| > 0.01, levels = 255
//   valid bin <=> bmin < bmax
// R14 delta vs R13 (66.0us):
//   - k_finalize deleted. k_reduce publishes block extrema via atomicMin/Max
//     on order-preserving uint-encoded floats (4 global cells).
//   - k_dequant decodes the cells and computes quant params inline per block.
//   - Replay-safe: cells statically init'd to encoded +-inf identities; the
//     LAST dequant block (ticket taken after all its work) resets cells+ticket.
//   - Reduce/dequant bodies identical to R12 measured-best.
// ---------------------------------------------------------------------------

#define THRESH 0.01f
#define RED_BLOCKS 2368          // 148 SMs * 16
#define RED_THREADS 256
#define DQ_THREADS 256
#define DQ_UNROLL 4

// Order-preserving float<->uint encoding:
//   enc monotone increasing in float value; min/max on uint == min/max on float.
#define ENC_POS_INF 0xFF800000u   // enc(+inf)  -> identity for atomicMin cells
#define ENC_NEG_INF 0x007FFFFFu   // enc(-inf)  -> identity for atomicMax cells

__device__ unsigned int g_smin_e = ENC_POS_INF;
__device__ unsigned int g_smax_e = ENC_NEG_INF;
__device__ unsigned int g_lmin_e = ENC_POS_INF;
__device__ unsigned int g_lmax_e = ENC_NEG_INF;
__device__ unsigned int g_tick  = 0;

__device__ __forceinline__ unsigned int enc_f(float x) {
    int b = __float_as_int(x);
    return (b >= 0) ? ((unsigned int)b | 0x80000000u) : ~(unsigned int)b;
}
__device__ __forceinline__ float dec_f(unsigned int u) {
    return (u & 0x80000000u) ? __uint_as_float(u & 0x7FFFFFFFu)
                             : __uint_as_float(~u);
}

struct MM { float smin, smax, lmin, lmax; };

__device__ __forceinline__ void mm_init(MM& m) {
    float inf = CUDART_INF_F;
    m.smin = inf; m.smax = -inf; m.lmin = inf; m.lmax = -inf;
}

// R3-proven branchless form: FSETP + 4 FSEL + 4 FMNMX (measured best).
__device__ __forceinline__ void acc_val(float x, MM& m) {
    bool big = fabsf(x) > THRESH;
    float inf = CUDART_INF_F;
    m.smin = fminf(m.smin, big ?  inf : x);
    m.smax = fmaxf(m.smax, big ? -inf : x);
    m.lmin = fminf(m.lmin, big ? x :  inf);
    m.lmax = fmaxf(m.lmax, big ? x : -inf);
}

__device__ __forceinline__ void acc_vec(float4 v, MM& m) {
    acc_val(v.x, m); acc_val(v.y, m); acc_val(v.z, m); acc_val(v.w, m);
}

__device__ __forceinline__ void mm_merge(MM& a, const MM& b) {
    a.smin = fminf(a.smin, b.smin);
    a.smax = fmaxf(a.smax, b.smax);
    a.lmin = fminf(a.lmin, b.lmin);
    a.lmax = fmaxf(a.lmax, b.lmax);
}

__device__ __forceinline__ void warp_reduce(MM& m) {
    #pragma unroll
    for (int o = 16; o > 0; o >>= 1) {
        m.smin = fminf(m.smin, __shfl_xor_sync(0xffffffffu, m.smin, o));
        m.smax = fmaxf(m.smax, __shfl_xor_sync(0xffffffffu, m.smax, o));
        m.lmin = fminf(m.lmin, __shfl_xor_sync(0xffffffffu, m.lmin, o));
        m.lmax = fmaxf(m.lmax, __shfl_xor_sync(0xffffffffu, m.lmax, o));
    }
}

__device__ __forceinline__ MM block_reduce(MM m) {
    warp_reduce(m);
    __shared__ MM sm[RED_THREADS / 32];
    int w = threadIdx.x >> 5;
    if ((threadIdx.x & 31) == 0) sm[w] = m;
    __syncthreads();
    MM r = sm[0];
    if (threadIdx.x == 0) {
        #pragma unroll
        for (int i = 1; i < RED_THREADS / 32; i++) mm_merge(r, sm[i]);
    }
    return r;
}

__global__ void __launch_bounds__(RED_THREADS)
k_reduce(const float* __restrict__ in, int n) {
    MM m0, m1, m2, m3;
    mm_init(m0); mm_init(m1); mm_init(m2); mm_init(m3);
    int nvec = n >> 2;
    const float4* __restrict__ in4 = (const float4*)in;
    int S = gridDim.x * blockDim.x;
    int tid = blockIdx.x * blockDim.x + threadIdx.x;
    int i = tid;
    for (; i + 3 * S < nvec; i += 4 * S) {
        float4 v0 = in4[i];
        float4 v1 = in4[i + S];
        float4 v2 = in4[i + 2 * S];
        float4 v3 = in4[i + 3 * S];
        acc_vec(v0, m0); acc_vec(v1, m1); acc_vec(v2, m2); acc_vec(v3, m3);
    }
    for (; i < nvec; i += S) acc_vec(in4[i], m0);
    if (blockIdx.x == 0) {
        for (int j = (nvec << 2) + threadIdx.x; j < n; j += blockDim.x)
            acc_val(in[j], m0);
    }
    mm_merge(m0, m1); mm_merge(m2, m3); mm_merge(m0, m2);
    MM r = block_reduce(m0);
    if (threadIdx.x == 0) {
        // +-inf block extrema encode to the cell identities -> harmless.
        atomicMin(&g_smin_e, enc_f(r.smin));
        atomicMax(&g_smax_e, enc_f(r.smax));
        atomicMin(&g_lmin_e, enc_f(r.lmin));
        atomicMax(&g_lmax_e, enc_f(r.lmax));
    }
}

__device__ __forceinline__ float dq(float x,
                                    float sbmin, float ssc, float siv, float svd,
                                    float lbmin, float lsc, float liv, float lvd) {
    bool big = fabsf(x) > THRESH;
    float bmin = big ? lbmin : sbmin;
    float sc   = big ? lsc   : ssc;
    float iv   = big ? liv   : siv;
    float vd   = big ? lvd   : svd;
    float q = rintf((x - bmin) * sc);   // rintf == round-half-even == jnp.round
    float d = fmaf(q, iv, bmin);
    return (vd != 0.0f) ? d : x;
}

// Reversed block order (L2-hot tail first) + evict-first stores; params
// decoded from the atomic cells inline; last block resets cells for replay.
__global__ void __launch_bounds__(DQ_THREADS)
k_dequant(const float* __restrict__ in, float* __restrict__ out, int n) {
    // Decode params (same-address broadcast loads; identical in all threads).
    float smin = dec_f(g_smin_e);
    float smax = dec_f(g_smax_e);
    float lmin = dec_f(g_lmin_e);
    float lmax = dec_f(g_lmax_e);
    bool sv = smin < smax;
    float sd = sv ? (smax - smin) : 1.0f;
    float ssc = 15.0f / sd, siv = sd / 15.0f, svd = sv ? 1.0f : 0.0f;
    bool lv = lmin < lmax;
    float ld = lv ? (lmax - lmin) : 1.0f;
    float lsc = 255.0f / ld, liv = ld / 255.0f, lvd = lv ? 1.0f : 0.0f;

    int nvec = n >> 2;
    const float4* __restrict__ in4 = (const float4*)in;
    float4* __restrict__ out4 = (float4*)out;
    int rb = gridDim.x - 1 - blockIdx.x;
    int base = rb * (DQ_UNROLL * DQ_THREADS) + threadIdx.x;

    int idx[DQ_UNROLL];
    float4 v[DQ_UNROLL];
    bool ok[DQ_UNROLL];
    #pragma unroll
    for (int u = 0; u < DQ_UNROLL; u++) {
        idx[u] = base + u * DQ_THREADS;
        ok[u] = idx[u] < nvec;
        if (ok[u]) v[u] = in4[idx[u]];
    }
    #pragma unroll
    for (int u = 0; u < DQ_UNROLL; u++) {
        if (ok[u]) {
            float4 r;
            r.x = dq(v[u].x, smin, ssc, siv, svd, lmin, lsc, liv, lvd);
            r.y = dq(v[u].y, smin, ssc, siv, svd, lmin, lsc, liv, lvd);
            r.z = dq(v[u].z, smin, ssc, siv, svd, lmin, lsc, liv, lvd);
            r.w = dq(v[u].w, smin, ssc, siv, svd, lmin, lsc, liv, lvd);
            __stcs(&out4[idx[u]], r);
        }
    }
    if (blockIdx.x == 0) {
        for (int j = (nvec << 2) + threadIdx.x; j < n; j += blockDim.x)
            __stcs(&out[j], dq(in[j], smin, ssc, siv, svd, lmin, lsc, liv, lvd));
    }

    // Replay-safe reset: last block to finish restores identities + ticket.
    __syncthreads();  // all this block's work (incl. param reads) done
    if (threadIdx.x == 0) {
        unsigned int old = atomicAdd(&g_tick, 1u);
        if (old == (unsigned int)(gridDim.x - 1)) {
            g_smin_e = ENC_POS_INF;
            g_smax_e = ENC_NEG_INF;
            g_lmin_e = ENC_POS_INF;
            g_lmax_e = ENC_NEG_INF;
            g_tick = 0;
        }
    }
}

extern "C" void kernel_launch(void* const* d_in, const int* in_sizes, int n_in,
                              void* d_out, int out_size) {
    (void)n_in; (void)out_size;
    const float* in = (const float*)d_in[0];
    float* out = (float*)d_out;
    int n = in_sizes[0];

    int nvec = n >> 2;

    k_reduce<<<RED_BLOCKS, RED_THREADS>>>(in, n);

    int chunk = DQ_UNROLL * DQ_THREADS;
    int dq_blocks = (nvec + chunk - 1) / chunk;
    if (dq_blocks < 1) dq_blocks = 1;
    k_dequant<<<dq_blocks, DQ_THREADS>>>(in, out, n);
}

// round 17
// speedup vs baseline: 1.0141x; 1.0141x over previous
#include <cuda_runtime.h>
#include <math.h>
#include <math_constants.h>

#ifndef CUDART_INF_F
#define CUDART_INF_F __int_as_float(0x7f800000)
#endif

// ---------------------------------------------------------------------------
// AdaptivePrecisionKVCache — R15: two-kernel pipeline; finalize folded into
// k_reduce's LAST block (4-cell read, not a partials re-reduce).
//   small bin: |x| <= 0.01, levels = 15 ; large bin: |x| > 0.01, levels = 255
//   valid bin <=> bmin < bmax
// R15 delta vs R14 (67.0us):
//   - k_dequant reverted to the R13 measured-best body (35.2us): params read
//     as two float4s, no inline divisions, no end-of-kernel ticket.
//   - k_reduce's last block (atomic ticket) computes g_ps/g_pl from the 4
//     encoded atomic cells and resets cells+ticket (graph-replay safe).
// ---------------------------------------------------------------------------

#define THRESH 0.01f
#define RED_BLOCKS 2368          // 148 SMs * 16
#define RED_THREADS 256
#define DQ_THREADS 256
#define DQ_UNROLL 4

// Order-preserving float<->uint encoding (monotone; uint min/max == float min/max).
#define ENC_POS_INF 0xFF800000u   // enc(+inf) -> identity for atomicMin cells
#define ENC_NEG_INF 0x007FFFFFu   // enc(-inf) -> identity for atomicMax cells

__device__ unsigned int g_smin_e = ENC_POS_INF;
__device__ unsigned int g_smax_e = ENC_NEG_INF;
__device__ unsigned int g_lmin_e = ENC_POS_INF;
__device__ unsigned int g_lmax_e = ENC_NEG_INF;
__device__ unsigned int g_tick  = 0;

__device__ float4 g_ps;   // smin, 15/sden, sden/15, svalid
__device__ float4 g_pl;   // lmin, 255/lden, lden/255, lvalid

__device__ __forceinline__ unsigned int enc_f(float x) {
    int b = __float_as_int(x);
    return (b >= 0) ? ((unsigned int)b | 0x80000000u) : ~(unsigned int)b;
}
__device__ __forceinline__ float dec_f(unsigned int u) {
    return (u & 0x80000000u) ? __uint_as_float(u & 0x7FFFFFFFu)
                             : __uint_as_float(~u);
}

struct MM { float smin, smax, lmin, lmax; };

__device__ __forceinline__ void mm_init(MM& m) {
    float inf = CUDART_INF_F;
    m.smin = inf; m.smax = -inf; m.lmin = inf; m.lmax = -inf;
}

// R3-proven branchless form: FSETP + 4 FSEL + 4 FMNMX (measured best).
__device__ __forceinline__ void acc_val(float x, MM& m) {
    bool big = fabsf(x) > THRESH;
    float inf = CUDART_INF_F;
    m.smin = fminf(m.smin, big ?  inf : x);
    m.smax = fmaxf(m.smax, big ? -inf : x);
    m.lmin = fminf(m.lmin, big ? x :  inf);
    m.lmax = fmaxf(m.lmax, big ? x : -inf);
}

__device__ __forceinline__ void acc_vec(float4 v, MM& m) {
    acc_val(v.x, m); acc_val(v.y, m); acc_val(v.z, m); acc_val(v.w, m);
}

__device__ __forceinline__ void mm_merge(MM& a, const MM& b) {
    a.smin = fminf(a.smin, b.smin);
    a.smax = fmaxf(a.smax, b.smax);
    a.lmin = fminf(a.lmin, b.lmin);
    a.lmax = fmaxf(a.lmax, b.lmax);
}

__device__ __forceinline__ void warp_reduce(MM& m) {
    #pragma unroll
    for (int o = 16; o > 0; o >>= 1) {
        m.smin = fminf(m.smin, __shfl_xor_sync(0xffffffffu, m.smin, o));
        m.smax = fmaxf(m.smax, __shfl_xor_sync(0xffffffffu, m.smax, o));
        m.lmin = fminf(m.lmin, __shfl_xor_sync(0xffffffffu, m.lmin, o));
        m.lmax = fmaxf(m.lmax, __shfl_xor_sync(0xffffffffu, m.lmax, o));
    }
}

__device__ __forceinline__ MM block_reduce(MM m) {
    warp_reduce(m);
    __shared__ MM sm[RED_THREADS / 32];
    int w = threadIdx.x >> 5;
    if ((threadIdx.x & 31) == 0) sm[w] = m;
    __syncthreads();
    MM r = sm[0];
    if (threadIdx.x == 0) {
        #pragma unroll
        for (int i = 1; i < RED_THREADS / 32; i++) mm_merge(r, sm[i]);
    }
    return r;
}

__global__ void __launch_bounds__(RED_THREADS)
k_reduce(const float* __restrict__ in, int n) {
    MM m0, m1, m2, m3;
    mm_init(m0); mm_init(m1); mm_init(m2); mm_init(m3);
    int nvec = n >> 2;
    const float4* __restrict__ in4 = (const float4*)in;
    int S = gridDim.x * blockDim.x;
    int tid = blockIdx.x * blockDim.x + threadIdx.x;
    int i = tid;
    for (; i + 3 * S < nvec; i += 4 * S) {
        float4 v0 = in4[i];
        float4 v1 = in4[i + S];
        float4 v2 = in4[i + 2 * S];
        float4 v3 = in4[i + 3 * S];
        acc_vec(v0, m0); acc_vec(v1, m1); acc_vec(v2, m2); acc_vec(v3, m3);
    }
    for (; i < nvec; i += S) acc_vec(in4[i], m0);
    if (blockIdx.x == 0) {
        for (int j = (nvec << 2) + threadIdx.x; j < n; j += blockDim.x)
            acc_val(in[j], m0);
    }
    mm_merge(m0, m1); mm_merge(m2, m3); mm_merge(m0, m2);
    MM r = block_reduce(m0);
    if (threadIdx.x == 0) {
        // Publish block extrema (+-inf encodes to cell identities -> harmless).
        atomicMin(&g_smin_e, enc_f(r.smin));
        atomicMax(&g_smax_e, enc_f(r.smax));
        atomicMin(&g_lmin_e, enc_f(r.lmin));
        atomicMax(&g_lmax_e, enc_f(r.lmax));
        __threadfence();                       // order cell pubs before ticket
        unsigned int old = atomicAdd(&g_tick, 1u);
        if (old == (unsigned int)(gridDim.x - 1)) {
            // All blocks' cell updates are visible (each fenced before ticket).
            float smin = dec_f(__ldcg(&g_smin_e));
            float smax = dec_f(__ldcg(&g_smax_e));
            float lmin = dec_f(__ldcg(&g_lmin_e));
            float lmax = dec_f(__ldcg(&g_lmax_e));
            bool sv = smin < smax;
            float sd = sv ? (smax - smin) : 1.0f;
            g_ps = make_float4(smin, 15.0f / sd, sd / 15.0f, sv ? 1.0f : 0.0f);
            bool lv = lmin < lmax;
            float ld = lv ? (lmax - lmin) : 1.0f;
            g_pl = make_float4(lmin, 255.0f / ld, ld / 255.0f, lv ? 1.0f : 0.0f);
            // Reset for next graph replay (kernel boundary publishes all this).
            g_smin_e = ENC_POS_INF;
            g_smax_e = ENC_NEG_INF;
            g_lmin_e = ENC_POS_INF;
            g_lmax_e = ENC_NEG_INF;
            g_tick = 0;
        }
    }
}

__device__ __forceinline__ float dq(float x, float4 ps, float4 pl) {
    bool big = fabsf(x) > THRESH;
    float bmin = big ? pl.x : ps.x;
    float sc   = big ? pl.y : ps.y;
    float iv   = big ? pl.z : ps.z;
    float vd   = big ? pl.w : ps.w;
    float q = rintf((x - bmin) * sc);   // rintf == round-half-even == jnp.round
    float d = fmaf(q, iv, bmin);
    return (vd != 0.0f) ? d : x;
}

__device__ __forceinline__ float4 dq4(float4 v, float4 ps, float4 pl) {
    v.x = dq(v.x, ps, pl);
    v.y = dq(v.y, ps, pl);
    v.z = dq(v.z, ps, pl);
    v.w = dq(v.w, ps, pl);
    return v;
}

// R13 measured-best body: reversed block order + evict-first stores.
__global__ void __launch_bounds__(DQ_THREADS)
k_dequant(const float* __restrict__ in, float* __restrict__ out, int n) {
    const float4 ps = g_ps;
    const float4 pl = g_pl;
    int nvec = n >> 2;
    const float4* __restrict__ in4 = (const float4*)in;
    float4* __restrict__ out4 = (float4*)out;
    int rb = gridDim.x - 1 - blockIdx.x;
    int base = rb * (DQ_UNROLL * DQ_THREADS) + threadIdx.x;

    int idx[DQ_UNROLL];
    float4 v[DQ_UNROLL];
    bool ok[DQ_UNROLL];
    #pragma unroll
    for (int u = 0; u < DQ_UNROLL; u++) {
        idx[u] = base + u * DQ_THREADS;
        ok[u] = idx[u] < nvec;
        if (ok[u]) v[u] = in4[idx[u]];
    }
    #pragma unroll
    for (int u = 0; u < DQ_UNROLL; u++) {
        if (ok[u]) __stcs(&out4[idx[u]], dq4(v[u], ps, pl));
    }
    if (blockIdx.x == 0) {
        for (int j = (nvec << 2) + threadIdx.x; j < n; j += blockDim.x)
            __stcs(&out[j], dq(in[j], ps, pl));
    }
}

extern "C" void kernel_launch(void* const* d_in, const int* in_sizes, int n_in,
                              void* d_out, int out_size) {
    (void)n_in; (void)out_size;
    const float* in = (const float*)d_in[0];
    float* out = (float*)d_out;
    int n = in_sizes[0];

    int nvec = n >> 2;

    k_reduce<<<RED_BLOCKS, RED_THREADS>>>(in, n);

    int chunk = DQ_UNROLL * DQ_THREADS;
    int dq_blocks = (nvec + chunk - 1) / chunk;
    if (dq_blocks < 1) dq_blocks = 1;
    k_dequant<<<dq_blocks, DQ_THREADS>>>(in, out, n);
}